// round 6
// baseline (speedup 1.0000x reference)
#include <cuda_runtime.h>
#include <cstdint>

// Problem constants
#define EXPERTS 16
#define CIN     16
#define COUT    64
#define HW      16384            // 128*128
#define NPIX    131072           // 8*128*128
#define MAXPE   131072
#define LOGIT_OFF   8388608
#define CHUNK   512              // pixels per expert block
#define NCHUNK  256              // 131072 / 512

// ---------------- scratch (device globals; no allocation) ----------------
__device__ int   g_cnt[EXPERTS];
__device__ int   g_pix[EXPERTS * MAXPE];
__device__ float g_gw [EXPERTS * MAXPE];

// ---------------- f32x2 packed math helpers ----------------
__device__ __forceinline__ unsigned long long pack2(float lo, float hi) {
    unsigned long long r;
    asm("mov.b64 %0, {%1, %2};" : "=l"(r) : "f"(lo), "f"(hi));
    return r;
}
__device__ __forceinline__ void fma2(unsigned long long& d, unsigned long long a, unsigned long long b) {
    asm("fma.rn.f32x2 %0, %1, %2, %0;" : "+l"(d) : "l"(a), "l"(b));
}
__device__ __forceinline__ float lo2(unsigned long long v) { return __uint_as_float((unsigned)(v & 0xFFFFFFFFull)); }
__device__ __forceinline__ float hi2(unsigned long long v) { return __uint_as_float((unsigned)(v >> 32)); }

// ---------------- kernel 0: reset counters ----------------
__global__ void reset_kernel() {
    if (threadIdx.x < EXPERTS) g_cnt[threadIdx.x] = 0;
}

// ---------------- kernel 1: zero out region ----------------
__global__ void zero_out_kernel(float4* __restrict__ out4) {
    int i = blockIdx.x * 256 + threadIdx.x;
    out4[i] = make_float4(0.f, 0.f, 0.f, 0.f);
}

// ---------------- kernel 2: gate ----------------
__global__ void gate_kernel(const float* __restrict__ x,
                            const float* __restrict__ gw,
                            const float* __restrict__ gb,
                            float* __restrict__ out_logits) {
    __shared__ float sgw[256];
    __shared__ float sgb[16];
    __shared__ int   scnt[16];
    __shared__ int   sbase[16];
    int tid = threadIdx.x;
    sgw[tid] = gw[tid];
    if (tid < 16) { sgb[tid] = gb[tid]; scnt[tid] = 0; }
    __syncthreads();

    int p  = blockIdx.x * 256 + tid;
    int b  = p >> 14;
    int hw = p & (HW - 1);

    float xv[CIN];
#pragma unroll
    for (int c = 0; c < CIN; c++) xv[c] = x[(b * CIN + c) * HW + hw];

    float best = -1e30f, second = -1e30f;
    int bi = 0, si = 0;
#pragma unroll
    for (int o = 0; o < 16; o++) {
        float l = sgb[o];
#pragma unroll
        for (int c = 0; c < CIN; c++) l = fmaf(sgw[o * 16 + c], xv[c], l);
        out_logits[(b * 16 + o) * HW + hw] = l;
        if (l > best) { second = best; si = bi; best = l; bi = o; }
        else if (l > second) { second = l; si = o; }
    }
    float w0 = 1.0f / (1.0f + expf(second - best));
    float w1 = 1.0f - w0;

    int l0 = atomicAdd(&scnt[bi], 1);
    int l1 = atomicAdd(&scnt[si], 1);
    __syncthreads();
    if (tid < 16) sbase[tid] = atomicAdd(&g_cnt[tid], scnt[tid]);
    __syncthreads();

    int q0 = sbase[bi] + l0;
    g_pix[bi * MAXPE + q0] = p;
    g_gw [bi * MAXPE + q0] = w0;
    int q1 = sbase[si] + l1;
    g_pix[si * MAXPE + q1] = p;
    g_gw [si * MAXPE + q1] = w1;
}

// ---------------- kernel 3: expert conv, GEMM register tiling ----------------
// block = 256 threads = 8 warps. warp = cout-group (8 couts), lane = pixel slot.
// Thread tile: 16 pixels (slots lane+32j) x 8 couts. Block: 512 pixels x 64 couts.
// Shared: weights [144][64] (36 KB) + bias + x-stage A[2][9][512] (36 KB).
__global__ void __launch_bounds__(256, 1)
expert_kernel(const float* __restrict__ x,
              const float* __restrict__ ew,
              const float* __restrict__ eb,
              float* __restrict__ out) {
    extern __shared__ float smem[];
    float* wsm = smem;                 // 144*64 = 9216 floats
    float* bsm = smem + 9216;          // 64
    float* As  = smem + 9280;          // 2*9*512 = 9216 floats

    int e = blockIdx.y;
    int n = g_cnt[e];
    int base = blockIdx.x * CHUNK;
    if (base >= n) return;

    int tid  = threadIdx.x;
    int lane = tid & 31;
    int cg   = tid >> 5;               // cout group 0..7, couts cg*8..cg*8+7

    // cooperative weight transpose into [ci*9+k][cout]
    const float* we = ew + e * (COUT * CIN * 9);
    for (int i = tid; i < 144 * 64; i += 256) {
        int cout = i & 63;
        int cik  = i >> 6;
        wsm[i] = we[cout * 144 + cik];
    }
    if (tid < 64) bsm[tid] = eb[e * 64 + tid];

    // per-thread staging pixels: sp0 = 2*tid, sp1 = 2*tid+1  (covers 512)
    int sidx0 = base + 2 * tid;
    int sidx1 = sidx0 + 1;
    bool sv0 = sidx0 < n, sv1 = sidx1 < n;
    int sp0p = sv0 ? g_pix[e * MAXPE + sidx0] : 0;
    int sp1p = sv1 ? g_pix[e * MAXPE + sidx1] : 0;
    // decode once
    int b0 = sp0p >> 14, hw0 = sp0p & (HW - 1), h0 = hw0 >> 7, w0 = hw0 & 127;
    int b1 = sp1p >> 14, hw1 = sp1p & (HW - 1), h1 = hw1 >> 7, w1 = hw1 & 127;
    const float* xb0 = x + b0 * (CIN * HW) + hw0;
    const float* xb1 = x + b1 * (CIN * HW) + hw1;
    bool hm0 = h0 > 0, hp0 = h0 < 127, wm0 = w0 > 0, wp0 = w0 < 127;
    bool hm1 = h1 > 0, hp1 = h1 < 127, wm1 = w1 > 0, wp1 = w1 < 127;

#define TAPS(tv, xc, v, hm, hp, wm, wp)                         \
    do {                                                        \
        tv[0] = (v && hm && wm) ? (xc)[-129] : 0.f;             \
        tv[1] = (v && hm)       ? (xc)[-128] : 0.f;             \
        tv[2] = (v && hm && wp) ? (xc)[-127] : 0.f;             \
        tv[3] = (v && wm)       ? (xc)[-1]   : 0.f;             \
        tv[4] =  v              ? (xc)[0]    : 0.f;             \
        tv[5] = (v && wp)       ? (xc)[1]    : 0.f;             \
        tv[6] = (v && hp && wm) ? (xc)[127]  : 0.f;             \
        tv[7] = (v && hp)       ? (xc)[128]  : 0.f;             \
        tv[8] = (v && hp && wp) ? (xc)[129]  : 0.f;             \
    } while (0)

    // stage ci = 0 into buffer 0
    {
        float t0[9], t1[9];
        TAPS(t0, xb0, sv0, hm0, hp0, wm0, wp0);
        TAPS(t1, xb1, sv1, hm1, hp1, wm1, wp1);
#pragma unroll
        for (int k = 0; k < 9; k++) {
            As[k * 512 + 2 * tid]     = t0[k];
            As[k * 512 + 2 * tid + 1] = t1[k];
        }
    }
    __syncthreads();

    // accumulators: 16 pixels x 4 f32x2 (8 couts), init with bias
    unsigned long long acc[16][4];
    {
        const float* bb = bsm + cg * 8;
        unsigned long long b01 = pack2(bb[0], bb[1]);
        unsigned long long b23 = pack2(bb[2], bb[3]);
        unsigned long long b45 = pack2(bb[4], bb[5]);
        unsigned long long b67 = pack2(bb[6], bb[7]);
#pragma unroll
        for (int j = 0; j < 16; j++) {
            acc[j][0] = b01; acc[j][1] = b23; acc[j][2] = b45; acc[j][3] = b67;
        }
    }

    int buf = 0;
#pragma unroll 1
    for (int ci = 0; ci < CIN; ci++) {
        // prefetch taps for ci+1 (LDG latency hidden behind the FMA block)
        float t0[9], t1[9];
        if (ci < CIN - 1) {
            const float* xc0 = xb0 + (ci + 1) * HW;
            const float* xc1 = xb1 + (ci + 1) * HW;
            TAPS(t0, xc0, sv0, hm0, hp0, wm0, wp0);
            TAPS(t1, xc1, sv1, hm1, hp1, wm1, wp1);
        }

        const float* Ab = As + buf * (9 * 512);
        const float* wrow = wsm + ci * 9 * 64 + cg * 8;
#pragma unroll
        for (int k = 0; k < 9; k++) {
            // 16 conflict-free per-lane-distinct x loads
            float xv[16];
            const float* Ak = Ab + k * 512 + lane;
#pragma unroll
            for (int j = 0; j < 16; j++) xv[j] = Ak[32 * j];
            // 8 broadcast weight floats (2x LDS.128)
            float4 wA = *(const float4*)(wrow + k * 64);
            float4 wB = *(const float4*)(wrow + k * 64 + 4);
            unsigned long long w01 = pack2(wA.x, wA.y);
            unsigned long long w23 = pack2(wA.z, wA.w);
            unsigned long long w45 = pack2(wB.x, wB.y);
            unsigned long long w67 = pack2(wB.z, wB.w);
#pragma unroll
            for (int j = 0; j < 16; j++) {
                unsigned long long xx = pack2(xv[j], xv[j]);
                fma2(acc[j][0], xx, w01);
                fma2(acc[j][1], xx, w23);
                fma2(acc[j][2], xx, w45);
                fma2(acc[j][3], xx, w67);
            }
        }

        if (ci < CIN - 1) {
            float* An = As + (buf ^ 1) * (9 * 512);
#pragma unroll
            for (int k = 0; k < 9; k++) {
                An[k * 512 + 2 * tid]     = t0[k];
                An[k * 512 + 2 * tid + 1] = t1[k];
            }
            __syncthreads();
            buf ^= 1;
        }
    }
#undef TAPS

    // epilogue: weighted atomic scatter (exactly 2 adds per output element)
#pragma unroll 1
    for (int j = 0; j < 16; j++) {
        int idx = base + lane + 32 * j;
        if (idx >= n) continue;
        int   p   = g_pix[e * MAXPE + idx];
        float gwt = g_gw [e * MAXPE + idx];
        int pb  = p >> 14;
        int phw = p & (HW - 1);
        float* ob = out + (pb * COUT + cg * 8) * HW + phw;
#pragma unroll
        for (int c = 0; c < 4; c++) {
            atomicAdd(&ob[(2 * c)     * HW], gwt * lo2(acc[j][c]));
            atomicAdd(&ob[(2 * c + 1) * HW], gwt * hi2(acc[j][c]));
        }
    }
}

// ---------------- launch ----------------
extern "C" void kernel_launch(void* const* d_in, const int* in_sizes, int n_in,
                              void* d_out, int out_size) {
    const float* x  = (const float*)d_in[0];
    const float* gw = (const float*)d_in[1];
    const float* gb = (const float*)d_in[2];
    const float* ew = (const float*)d_in[3];
    const float* eb = (const float*)d_in[4];
    float* out    = (float*)d_out;
    float* logits = out + LOGIT_OFF;

    const int smem_bytes = (9216 + 64 + 9216) * 4;   // 73,984 B
    cudaFuncSetAttribute(expert_kernel,
                         cudaFuncAttributeMaxDynamicSharedMemorySize, smem_bytes);

    reset_kernel<<<1, 32>>>();
    zero_out_kernel<<<8192, 256>>>((float4*)out);
    gate_kernel<<<512, 256>>>(x, gw, gb, logits);
    expert_kernel<<<dim3(NCHUNK, EXPERTS), 256, smem_bytes>>>(x, ew, eb, out);
    (void)in_sizes; (void)n_in; (void)out_size;
}

// round 8
// speedup vs baseline: 1.2287x; 1.2287x over previous
#include <cuda_runtime.h>
#include <cstdint>

// Problem constants
#define EXPERTS 16
#define CIN     16
#define COUT    64
#define HW      16384            // 128*128
#define NPIX    131072           // 8*128*128
#define MAXPE   131072
#define LOGIT_OFF   8388608
#define CHUNK   256              // pixels per expert block
#define NCHUNK  512              // 131072 / 256 (max chunks per expert)

// ---------------- scratch (device globals; no allocation) ----------------
__device__ int   g_cnt[EXPERTS];
__device__ int   g_pix[EXPERTS * MAXPE];
__device__ float g_gw [EXPERTS * MAXPE];

// ---------------- f32x2 packed math helpers ----------------
__device__ __forceinline__ unsigned long long pack2(float lo, float hi) {
    unsigned long long r;
    asm("mov.b64 %0, {%1, %2};" : "=l"(r) : "f"(lo), "f"(hi));
    return r;
}
__device__ __forceinline__ void fma2(unsigned long long& d, unsigned long long a, unsigned long long b) {
    asm("fma.rn.f32x2 %0, %1, %2, %0;" : "+l"(d) : "l"(a), "l"(b));
}
__device__ __forceinline__ float lo2(unsigned long long v) { return __uint_as_float((unsigned)(v & 0xFFFFFFFFull)); }
__device__ __forceinline__ float hi2(unsigned long long v) { return __uint_as_float((unsigned)(v >> 32)); }

// ---------------- kernel 0: reset counters ----------------
__global__ void reset_kernel() {
    if (threadIdx.x < EXPERTS) g_cnt[threadIdx.x] = 0;
}

// ---------------- kernel 1: zero out region ----------------
__global__ void zero_out_kernel(float4* __restrict__ out4) {
    int i = blockIdx.x * 256 + threadIdx.x;
    out4[i] = make_float4(0.f, 0.f, 0.f, 0.f);
}

// ---------------- kernel 2: gate ----------------
__global__ void gate_kernel(const float* __restrict__ x,
                            const float* __restrict__ gw,
                            const float* __restrict__ gb,
                            float* __restrict__ out_logits) {
    __shared__ float sgw[256];
    __shared__ float sgb[16];
    __shared__ int   scnt[16];
    __shared__ int   sbase[16];
    int tid = threadIdx.x;
    sgw[tid] = gw[tid];
    if (tid < 16) { sgb[tid] = gb[tid]; scnt[tid] = 0; }
    __syncthreads();

    int p  = blockIdx.x * 256 + tid;
    int b  = p >> 14;
    int hw = p & (HW - 1);

    float xv[CIN];
#pragma unroll
    for (int c = 0; c < CIN; c++) xv[c] = x[(b * CIN + c) * HW + hw];

    float best = -1e30f, second = -1e30f;
    int bi = 0, si = 0;
#pragma unroll
    for (int o = 0; o < 16; o++) {
        float l = sgb[o];
#pragma unroll
        for (int c = 0; c < CIN; c++) l = fmaf(sgw[o * 16 + c], xv[c], l);
        out_logits[(b * 16 + o) * HW + hw] = l;
        if (l > best) { second = best; si = bi; best = l; bi = o; }
        else if (l > second) { second = l; si = o; }
    }
    // softmax + top-2 renorm collapses exactly: w0 = 1/(1+exp(l1-l0))
    float w0 = 1.0f / (1.0f + expf(second - best));
    float w1 = 1.0f - w0;

    int l0 = atomicAdd(&scnt[bi], 1);
    int l1 = atomicAdd(&scnt[si], 1);
    __syncthreads();
    if (tid < 16) sbase[tid] = atomicAdd(&g_cnt[tid], scnt[tid]);
    __syncthreads();

    int q0 = sbase[bi] + l0;
    g_pix[bi * MAXPE + q0] = p;
    g_gw [bi * MAXPE + q0] = w0;
    int q1 = sbase[si] + l1;
    g_pix[si * MAXPE + q1] = p;
    g_gw [si * MAXPE + q1] = w1;
}

// ---------------- kernel 3: expert conv, m=8 x n=8 register tile ----------------
// block = 256 threads = 8 warps; warp cg = cout group (8 couts), lane = pixel slot.
// Thread tile: 8 pixels (slots lane+32j) x 8 couts (32 u64 accs).
// Block tile: 256 pixels x 64 couts. Static smem 46.3 KB -> 2 CTAs/SM, 16 warps.
__global__ void __launch_bounds__(256, 2)
expert_kernel(const float* __restrict__ x,
              const float* __restrict__ ew,
              const float* __restrict__ eb,
              float* __restrict__ out) {
    __shared__ __align__(16) float wsm[144 * 64];   // [ci*9+k][cout]  36,864 B
    __shared__ float bsm[64];
    __shared__ float As[9 * 256];                    // x-stage [tap][pixel] 9,216 B

    int e = blockIdx.y;
    int n = g_cnt[e];
    int base = blockIdx.x * CHUNK;
    if (base >= n) return;

    int tid  = threadIdx.x;
    int lane = tid & 31;
    int cg   = tid >> 5;

    // cooperative weight transpose into [ci*9+k][cout]
    const float* we = ew + e * (COUT * CIN * 9);
#pragma unroll
    for (int i = tid; i < 144 * 64; i += 256) {
        int cout = i & 63;
        int cik  = i >> 6;
        wsm[i] = we[cout * 144 + cik];
    }
    if (tid < 64) bsm[tid] = eb[e * 64 + tid];

    // each thread stages exactly one pixel slot (= tid) per ci
    int sidx = base + tid;
    bool sv  = sidx < n;
    int sp   = sv ? g_pix[e * MAXPE + sidx] : 0;
    int sb  = sp >> 14, shw = sp & (HW - 1);
    int sh  = shw >> 7, sw = shw & 127;
    const float* xb = x + sb * (CIN * HW) + shw;
    bool hm = sh > 0, hp = sh < 127, wm = sw > 0, wp = sw < 127;

#define TAPS(tv, xc)                                            \
    do {                                                        \
        tv[0] = (sv && hm && wm) ? (xc)[-129] : 0.f;            \
        tv[1] = (sv && hm)       ? (xc)[-128] : 0.f;            \
        tv[2] = (sv && hm && wp) ? (xc)[-127] : 0.f;            \
        tv[3] = (sv && wm)       ? (xc)[-1]   : 0.f;            \
        tv[4] =  sv              ? (xc)[0]    : 0.f;            \
        tv[5] = (sv && wp)       ? (xc)[1]    : 0.f;            \
        tv[6] = (sv && hp && wm) ? (xc)[127]  : 0.f;            \
        tv[7] = (sv && hp)       ? (xc)[128]  : 0.f;            \
        tv[8] = (sv && hp && wp) ? (xc)[129]  : 0.f;            \
    } while (0)

    // stage ci = 0
    {
        float t[9];
        TAPS(t, xb);
#pragma unroll
        for (int k = 0; k < 9; k++) As[k * 256 + tid] = t[k];
    }
    __syncthreads();   // weights + bias + stage(ci=0) visible

    // accumulators: 8 pixels x 4 f32x2 (8 couts), init with bias
    unsigned long long acc[8][4];
    {
        const float* bb = bsm + cg * 8;
        unsigned long long b01 = pack2(bb[0], bb[1]);
        unsigned long long b23 = pack2(bb[2], bb[3]);
        unsigned long long b45 = pack2(bb[4], bb[5]);
        unsigned long long b67 = pack2(bb[6], bb[7]);
#pragma unroll
        for (int j = 0; j < 8; j++) {
            acc[j][0] = b01; acc[j][1] = b23; acc[j][2] = b45; acc[j][3] = b67;
        }
    }

#pragma unroll 1
    for (int ci = 0; ci < CIN; ci++) {
        // prefetch next ci's taps into registers (LDG hidden under FMA block)
        float t[9];
        if (ci < CIN - 1) {
            const float* xc = xb + (ci + 1) * HW;
            TAPS(t, xc);
        }

        const float* wrow = wsm + ci * 9 * 64 + cg * 8;
#pragma unroll
        for (int k = 0; k < 9; k++) {
            // 8 lane-distinct conflict-free x loads
            float xv[8];
            const float* Ak = As + k * 256 + lane;
#pragma unroll
            for (int j = 0; j < 8; j++) xv[j] = Ak[32 * j];
            // 8 broadcast weight floats (2x LDS.128)
            float4 wA = *(const float4*)(wrow + k * 64);
            float4 wB = *(const float4*)(wrow + k * 64 + 4);
            unsigned long long w01 = pack2(wA.x, wA.y);
            unsigned long long w23 = pack2(wA.z, wA.w);
            unsigned long long w45 = pack2(wB.x, wB.y);
            unsigned long long w67 = pack2(wB.z, wB.w);
#pragma unroll
            for (int j = 0; j < 8; j++) {
                unsigned long long xx = pack2(xv[j], xv[j]);
                fma2(acc[j][0], xx, w01);
                fma2(acc[j][1], xx, w23);
                fma2(acc[j][2], xx, w45);
                fma2(acc[j][3], xx, w67);
            }
        }

        if (ci < CIN - 1) {
            __syncthreads();   // everyone done reading As
#pragma unroll
            for (int k = 0; k < 9; k++) As[k * 256 + tid] = t[k];
            __syncthreads();   // stage(ci+1) visible
        }
    }
#undef TAPS

    // epilogue: weighted atomic scatter (exactly 2 commutative adds per output elem)
#pragma unroll 1
    for (int j = 0; j < 8; j++) {
        int idx = base + lane + 32 * j;
        if (idx >= n) continue;
        int   p   = g_pix[e * MAXPE + idx];
        float gwt = g_gw [e * MAXPE + idx];
        int pb  = p >> 14;
        int phw = p & (HW - 1);
        float* ob = out + (pb * COUT + cg * 8) * HW + phw;
#pragma unroll
        for (int c = 0; c < 4; c++) {
            atomicAdd(&ob[(2 * c)     * HW], gwt * lo2(acc[j][c]));
            atomicAdd(&ob[(2 * c + 1) * HW], gwt * hi2(acc[j][c]));
        }
    }
}

// ---------------- launch ----------------
extern "C" void kernel_launch(void* const* d_in, const int* in_sizes, int n_in,
                              void* d_out, int out_size) {
    const float* x  = (const float*)d_in[0];   // (8,16,128,128)
    const float* gw = (const float*)d_in[1];   // (16,16,1,1)
    const float* gb = (const float*)d_in[2];   // (16,)
    const float* ew = (const float*)d_in[3];   // (16,64,16,3,3)
    const float* eb = (const float*)d_in[4];   // (16,64)
    float* out    = (float*)d_out;
    float* logits = out + LOGIT_OFF;

    reset_kernel<<<1, 32>>>();
    zero_out_kernel<<<8192, 256>>>((float4*)out);
    gate_kernel<<<512, 256>>>(x, gw, gb, logits);
    expert_kernel<<<dim3(NCHUNK, EXPERTS), 256>>>(x, ew, eb, out);
    (void)in_sizes; (void)n_in; (void)out_size;
}